// round 8
// baseline (speedup 1.0000x reference)
#include <cuda_runtime.h>
#include <math.h>

#define S_ 8192
#define D_ 64
#define N_ 2048
#define O_ 8
#define GATHER_BLOCKS 256                 // 256 x 256 thr = 65536 = S_*O_
#define LSE_BLOCKS (2 * N_ + O_ + N_ / 8) // 4360

// ---- scratch (allocation-free rule: __device__ globals; BSS = 0) ----
__device__ float d_lse0[N_];
__device__ float d_lse1[N_];
__device__ float d_lse2[N_];
__device__ float d_lse_out[O_];
// one flag line per gather block (avoids R3/R4 single-line LTS contention)
__device__ unsigned d_flags[GATHER_BLOCKS * 32];
__device__ __align__(128) unsigned d_lse_done;   // LSE arrivals
__device__ __align__(128) unsigned d_g_done;     // gather arrivals (reset)

__device__ __forceinline__ unsigned ld_acquire_u32(const unsigned* p) {
    unsigned v;
    asm volatile("ld.acquire.gpu.u32 %0, [%1];" : "=r"(v) : "l"(p));
    return v;
}
__device__ __forceinline__ void st_release_u32(unsigned* p, unsigned v) {
    asm volatile("st.release.gpu.u32 [%0], %1;" :: "l"(p), "r"(v) : "memory");
}

// ---------------------------------------------------------------------------
// Single kernel.
//   blocks [0, GATHER_BLOCKS)  : FULL path walk -> BAR -> flag-wait -> normalize
//   remaining blocks           : row-wise logsumexp; last arrival broadcasts.
// CRITICAL FIX vs R3-R5: a __syncthreads() sits BETWEEN the walk and the spin.
// acquire is one-way (earlier ops may sink below it); without the barrier
// ptxas could sink the walk's loads past the unbounded poll loop, serializing
// walk-after-LSE (the 19-21us failures). BAR.SYNC pins the walk before it.
// ---------------------------------------------------------------------------
__global__ void __launch_bounds__(256) occamnet_kernel(const float* __restrict__ x,
                                                       const float* __restrict__ w0,
                                                       const float* __restrict__ w1,
                                                       const float* __restrict__ w2,
                                                       const float* __restrict__ w_out,
                                                       const int* __restrict__ c0,
                                                       const int* __restrict__ c1,
                                                       const int* __restrict__ c2,
                                                       const int* __restrict__ keys_out,
                                                       float* __restrict__ out)
{
    __shared__ float smax[8];
    __shared__ float ssum[8];
    __shared__ unsigned s_last;

    const int b = blockIdx.x;
    const int t = threadIdx.x;
    const int lane = t & 31;
    const int warp = t >> 5;

    if (b < GATHER_BLOCKS) {
        // ================= full path-walk gather =================
        const int tid = b * 256 + t;
        const int s = tid >> 3;          // / O_
        const int o = tid & 7;           // % O_

        const int r2 = keys_out[tid];
        float logp = w_out[o * N_ + r2];

        const int r1 = c2[(size_t)s * N_ + r2];
        logp += w2[(size_t)r2 * N_ + r1];

        const int r0 = c1[(size_t)s * N_ + r1];
        logp += w1[(size_t)r1 * N_ + r0];

        const int cin = c0[(size_t)s * N_ + r0];
        logp += w0[r0 * D_ + cin];

        const float y = __sinf(__sinf(__sinf(x[s * D_ + cin])));
        out[tid] = y;                                        // [0, S, O] slice

        // Pin the entire walk (loads + y store) BEFORE the spin.
        __syncthreads();

        unsigned* myflag = &d_flags[b * 32];
        if (t == 0) {
            while (ld_acquire_u32(myflag) == 0u)
                __nanosleep(128);
        }
        __syncthreads();

        // Tables written by other SMs this launch: bypass L1.
        logp -= __ldcg(&d_lse_out[o]) + __ldcg(&d_lse2[r2])
              + __ldcg(&d_lse1[r1])   + __ldcg(&d_lse0[r0]);
        out[S_ * O_ + tid] = __expf(logp);                   // [1, S, O] slice

        if (t == 0) {
            *myflag = 0u;                // self-reset for next graph replay
            unsigned old = atomicAdd(&d_g_done, 1u);
            if (old == GATHER_BLOCKS - 1) {                  // last gather block
                atomicExch(&d_lse_done, 0u);
                atomicExch(&d_g_done, 0u);
            }
        }
        return;
    }

    const int b2 = b - GATHER_BLOCKS;
    if (b2 < 2 * N_ + O_) {
        // ================= wide rows: 2048 elements =================
        const float* row;
        float* dst;
        if (b2 < N_)          { row = w1    + (size_t)b2 * N_;           dst = &d_lse1[b2]; }
        else if (b2 < 2 * N_) { row = w2    + (size_t)(b2 - N_) * N_;    dst = &d_lse2[b2 - N_]; }
        else                  { row = w_out + (size_t)(b2 - 2*N_) * N_;  dst = &d_lse_out[b2 - 2*N_]; }

        const float4* row4 = (const float4*)row;
        float4 a = row4[t];
        float4 c = row4[t + 256];
        float v[8] = {a.x, a.y, a.z, a.w, c.x, c.y, c.z, c.w};

        float m = v[0];
        #pragma unroll
        for (int i = 1; i < 8; i++) m = fmaxf(m, v[i]);
        #pragma unroll
        for (int off = 16; off; off >>= 1) m = fmaxf(m, __shfl_xor_sync(0xffffffffu, m, off));
        if (lane == 0) smax[warp] = m;
        __syncthreads();
        float bm = smax[0];
        #pragma unroll
        for (int i = 1; i < 8; i++) bm = fmaxf(bm, smax[i]);

        float ss = 0.0f;
        #pragma unroll
        for (int i = 0; i < 8; i++) ss += __expf(v[i] - bm);
        #pragma unroll
        for (int off = 16; off; off >>= 1) ss += __shfl_xor_sync(0xffffffffu, ss, off);
        if (lane == 0) ssum[warp] = ss;
        __syncthreads();
        if (t == 0) {
            float tot = 0.0f;
            #pragma unroll
            for (int i = 0; i < 8; i++) tot += ssum[i];
            *dst = bm + __logf(tot);
            __threadfence();                               // release row
            unsigned old = atomicAdd(&d_lse_done, 1u);     // arrive
            s_last = (old == (unsigned)LSE_BLOCKS - 1) ? 1u : 0u;
            if (s_last) __threadfence();                   // see all rows
        }
        __syncthreads();
        if (s_last)                                        // last LSE block:
            st_release_u32(&d_flags[t * 32], 1u);          // 256-wide broadcast
    } else {
        // ================= w0: 64-wide rows, one warp per row =================
        const int r = (b2 - (2 * N_ + O_)) * 8 + warp;
        const float* row = w0 + (size_t)r * D_;
        float v0 = row[lane];
        float v1 = row[lane + 32];
        float m = fmaxf(v0, v1);
        #pragma unroll
        for (int off = 16; off; off >>= 1) m = fmaxf(m, __shfl_xor_sync(0xffffffffu, m, off));
        float ss = __expf(v0 - m) + __expf(v1 - m);
        #pragma unroll
        for (int off = 16; off; off >>= 1) ss += __shfl_xor_sync(0xffffffffu, ss, off);
        if (lane == 0) d_lse0[r] = m + __logf(ss);
        __syncthreads();                                   // all 8 rows written
        if (t == 0) {
            __threadfence();                               // release
            unsigned old = atomicAdd(&d_lse_done, 1u);     // arrive
            s_last = (old == (unsigned)LSE_BLOCKS - 1) ? 1u : 0u;
            if (s_last) __threadfence();
        }
        __syncthreads();
        if (s_last)
            st_release_u32(&d_flags[t * 32], 1u);
    }
}

extern "C" void kernel_launch(void* const* d_in, const int* in_sizes, int n_in,
                              void* d_out, int out_size)
{
    const float* x     = (const float*)d_in[0];
    const float* w0    = (const float*)d_in[1];
    const float* w1    = (const float*)d_in[2];
    const float* w2    = (const float*)d_in[3];
    const float* w_out = (const float*)d_in[4];
    const int*   c0    = (const int*)d_in[5];
    const int*   c1    = (const int*)d_in[6];
    const int*   c2    = (const int*)d_in[7];
    const int*   keys  = (const int*)d_in[8];
    float*       out   = (float*)d_out;

    const int blocks = GATHER_BLOCKS + LSE_BLOCKS;
    occamnet_kernel<<<blocks, 256>>>(x, w0, w1, w2, w_out,
                                     c0, c1, c2, keys, out);
}

// round 10
// speedup vs baseline: 1.3652x; 1.3652x over previous
#include <cuda_runtime.h>
#include <math.h>

#define S_ 8192
#define D_ 64
#define N_ 2048
#define O_ 8
#define GATHER_BLOCKS 256                 // 256 x 256 thr = 65536 = S_*O_
#define SIN_BLOCKS 256                    // 131072 float4 / (256 thr * 2)
#define LSE_BLOCKS (2 * N_ + O_ + N_ / 8) // 4360

// ---- scratch (allocation-free rule: __device__ globals) ----
__device__ float d_lse0[N_];
__device__ float d_lse1[N_];
__device__ float d_lse2[N_];
__device__ float d_lse_out[O_];
__device__ float d_sy[S_ * D_];     // sin(sin(sin(x))) precomputed, coalesced
__device__ uint4 d_walk[S_ * O_];   // {bits(w_out+w2+w1), r2, r1, (r0<<16)|cin}

// ---------------------------------------------------------------------------
// Kernel A: LSE tables (MUFU-bound floor ~5.7us) + FULL index walk + sin3(x)
// precompute, all overlapped. Key facts from R1-R8:
//   * 3 dependent gather rounds hide under the LSE MUFU floor (R7).
//   * c0[s,r0] shares round 3 with w1[r1,r0] (both need r0) -> piggyback,
//     no added chain depth. B then has NO dependent DRAM hop left.
//   * sy precompute is coalesced + tiny MUFU add; turns B's cold x lookup
//     into an L2 hit.
// ---------------------------------------------------------------------------
__global__ void __launch_bounds__(256) lse_gather_kernel(const float* __restrict__ x,
                                                         const float* __restrict__ w0,
                                                         const float* __restrict__ w1,
                                                         const float* __restrict__ w2,
                                                         const float* __restrict__ w_out,
                                                         const int* __restrict__ c0,
                                                         const int* __restrict__ c1,
                                                         const int* __restrict__ c2,
                                                         const int* __restrict__ keys_out)
{
    __shared__ float smax[8];
    __shared__ float ssum[8];

    const int b = blockIdx.x;
    const int t = threadIdx.x;
    const int lane = t & 31;
    const int warp = t >> 5;

    if (b < GATHER_BLOCKS) {
        // ========== index walk: rounds 0-3, c0 piggybacked on round 3 ==========
        const int tid = b * 256 + t;
        const int s = tid >> 3;          // / O_
        const int o = tid & 7;           // % O_

        const int r2 = keys_out[tid];                       // round 0 (coalesced)
        float logp = w_out[o * N_ + r2];                    // round 1

        const int r1 = c2[(size_t)s * N_ + r2];             // round 1
        logp += w2[(size_t)r2 * N_ + r1];                   // round 2

        const int r0 = c1[(size_t)s * N_ + r1];             // round 2
        logp += w1[(size_t)r1 * N_ + r0];                   // round 3
        const int cin = c0[(size_t)s * N_ + r0];            // round 3 (piggyback)

        d_walk[tid] = make_uint4(__float_as_uint(logp),
                                 (unsigned)r2, (unsigned)r1,
                                 ((unsigned)r0 << 16) | (unsigned)cin);
        return;
    }

    if (b < GATHER_BLOCKS + SIN_BLOCKS) {
        // ===== sy = sin^3(x): 512 float4 per block, 2 per thread (R9 bug:
        // only the first 256 were written; fixed with the i-loop) =====
        const int b0 = (b - GATHER_BLOCKS) * 512;
        const float4* x4 = (const float4*)x;
        float4* sy4 = (float4*)d_sy;
        #pragma unroll
        for (int i = 0; i < 2; i++) {
            const int base = b0 + i * 256 + t;
            float4 v = x4[base];
            v.x = __sinf(__sinf(__sinf(v.x)));
            v.y = __sinf(__sinf(__sinf(v.y)));
            v.z = __sinf(__sinf(__sinf(v.z)));
            v.w = __sinf(__sinf(__sinf(v.w)));
            sy4[base] = v;
        }
        return;
    }

    const int b2 = b - GATHER_BLOCKS - SIN_BLOCKS;
    if (b2 < 2 * N_ + O_) {
        // ================= wide rows: 2048 elements =================
        const float* row;
        float* dst;
        if (b2 < N_)          { row = w1    + (size_t)b2 * N_;           dst = &d_lse1[b2]; }
        else if (b2 < 2 * N_) { row = w2    + (size_t)(b2 - N_) * N_;    dst = &d_lse2[b2 - N_]; }
        else                  { row = w_out + (size_t)(b2 - 2*N_) * N_;  dst = &d_lse_out[b2 - 2*N_]; }

        const float4* row4 = (const float4*)row;
        float4 a = row4[t];
        float4 c = row4[t + 256];
        float v[8] = {a.x, a.y, a.z, a.w, c.x, c.y, c.z, c.w};

        float m = v[0];
        #pragma unroll
        for (int i = 1; i < 8; i++) m = fmaxf(m, v[i]);
        #pragma unroll
        for (int off = 16; off; off >>= 1) m = fmaxf(m, __shfl_xor_sync(0xffffffffu, m, off));
        if (lane == 0) smax[warp] = m;
        __syncthreads();
        float bm = smax[0];
        #pragma unroll
        for (int i = 1; i < 8; i++) bm = fmaxf(bm, smax[i]);

        float ss = 0.0f;
        #pragma unroll
        for (int i = 0; i < 8; i++) ss += __expf(v[i] - bm);
        #pragma unroll
        for (int off = 16; off; off >>= 1) ss += __shfl_xor_sync(0xffffffffu, ss, off);
        if (lane == 0) ssum[warp] = ss;
        __syncthreads();
        if (t == 0) {
            float tot = 0.0f;
            #pragma unroll
            for (int i = 0; i < 8; i++) tot += ssum[i];
            *dst = bm + __logf(tot);
        }
    } else {
        // ================= w0: 64-wide rows, one warp per row =================
        const int r = (b2 - (2 * N_ + O_)) * 8 + warp;
        const float* row = w0 + (size_t)r * D_;
        float v0 = row[lane];
        float v1 = row[lane + 32];
        float m = fmaxf(v0, v1);
        #pragma unroll
        for (int off = 16; off; off >>= 1) m = fmaxf(m, __shfl_xor_sync(0xffffffffu, m, off));
        float ss = __expf(v0 - m) + __expf(v1 - m);
        #pragma unroll
        for (int off = 16; off; off >>= 1) ss += __shfl_xor_sync(0xffffffffu, ss, off);
        if (lane == 0) d_lse0[r] = m + __logf(ss);
    }
}

// ---------------------------------------------------------------------------
// Kernel B: ONE divergent round (all L2-hot: w0 warmed by A's LSE pass, sy
// written by A) + smem-staged normalize + coalesced stores. No DRAM hop.
// ---------------------------------------------------------------------------
__global__ void __launch_bounds__(256) finalize_kernel(const float* __restrict__ w0,
                                                       float* __restrict__ out)
{
    __shared__ float s_lse0[N_];
    __shared__ float s_lse1[N_];
    __shared__ float s_lse2[N_];
    __shared__ float s_lse_out[O_];

    const int t = threadIdx.x;
    const int tid = blockIdx.x * blockDim.x + t;
    const int s = tid >> 3;          // / O_
    const int o = tid & 7;           // % O_

    // issue the divergent (L2-hot) loads BEFORE the staging barrier
    const uint4 wlk = d_walk[tid];
    const int r2 = (int)wlk.y, r1 = (int)wlk.z;
    const int r0 = (int)(wlk.w >> 16), cin = (int)(wlk.w & 0xFFFFu);
    const float w0v = w0[r0 * D_ + cin];
    const float syv = d_sy[s * D_ + cin];

    // cooperative table staging (coalesced float4 from L2)
    const float4* g0 = (const float4*)d_lse0;
    const float4* g1 = (const float4*)d_lse1;
    const float4* g2 = (const float4*)d_lse2;
    #pragma unroll
    for (int i = 0; i < N_ / 4 / 256; i++) {      // 2 iters
        ((float4*)s_lse0)[t + i * 256] = g0[t + i * 256];
        ((float4*)s_lse1)[t + i * 256] = g1[t + i * 256];
        ((float4*)s_lse2)[t + i * 256] = g2[t + i * 256];
    }
    if (t < O_) s_lse_out[t] = d_lse_out[t];
    __syncthreads();

    const float logp = __uint_as_float(wlk.x) + w0v
                     - s_lse_out[o] - s_lse2[r2] - s_lse1[r1] - s_lse0[r0];

    out[tid] = syv;                               // [0, S, O] slice
    out[S_ * O_ + tid] = __expf(logp);            // [1, S, O] slice
}

extern "C" void kernel_launch(void* const* d_in, const int* in_sizes, int n_in,
                              void* d_out, int out_size)
{
    const float* x     = (const float*)d_in[0];
    const float* w0    = (const float*)d_in[1];
    const float* w1    = (const float*)d_in[2];
    const float* w2    = (const float*)d_in[3];
    const float* w_out = (const float*)d_in[4];
    const int*   c0    = (const int*)d_in[5];
    const int*   c1    = (const int*)d_in[6];
    const int*   c2    = (const int*)d_in[7];
    const int*   keys  = (const int*)d_in[8];
    float*       out   = (float*)d_out;

    const int blocksA = GATHER_BLOCKS + SIN_BLOCKS + LSE_BLOCKS;
    lse_gather_kernel<<<blocksA, 256>>>(x, w0, w1, w2, w_out,
                                        c0, c1, c2, keys);

    finalize_kernel<<<GATHER_BLOCKS, 256>>>(w0, out);
}